// round 7
// baseline (speedup 1.0000x reference)
#include <cuda_runtime.h>
#include <cuda_bf16.h>
#include <math_constants.h>

// SoftDiceLoss: probs [64,1,512,512] f32, targets same. Scalar f32 output.
//
// Single pass over both tensors. Per-sample monoid:
//   sums: sum_p, sum_t, sum_pt, cnt_le (count p<=0.5)
//   max-with-counts: (m, n1, n0) where m = max(t) so far,
//     n1 = #{t==m && p>0.5}, n0 = #{t==m && p<=0.5}
// Merge: bigger m wins; equal m sums counts.
// corr = n1 + cnt_le - n0;  acc = corr / C (C=1);
// dice = 2*(sum_pt+1)/(sum_p+sum_t+1); score = (acc==1) ? 1 : dice;
// loss = mean_b(1 - score).

static constexpr int B        = 64;
static constexpr int NPS      = 512 * 512;   // elements per sample (C=1)
static constexpr int BPS      = 16;          // blocks per sample (1024 CTAs: ~6.9/SM, small tail)
static constexpr int THREADS  = 256;
static constexpr int PER_BLK  = NPS / BPS;            // 16384
static constexpr int VEC_PER_THREAD = PER_BLK / (THREADS * 4);  // 16 float4

struct Partial {
    float sum_p, sum_t, sum_pt;
    int   cnt_le;
    float m;
    int   n1, n0;
};

__device__ Partial g_partials[B * BPS];

__device__ __forceinline__ void merge_max(float& m, int& n1, int& n0,
                                          float mo, int n1o, int n0o) {
    if (mo > m)        { m = mo; n1 = n1o; n0 = n0o; }
    else if (mo == m)  { n1 += n1o; n0 += n0o; }
}

__global__ __launch_bounds__(THREADS)
void sdl_pass1(const float* __restrict__ probs,
               const float* __restrict__ targets) {
    const int s  = blockIdx.x / BPS;       // sample
    const int bi = blockIdx.x % BPS;       // block within sample
    const int tid = threadIdx.x;

    const float4* p4 = reinterpret_cast<const float4*>(probs   + (size_t)s * NPS + (size_t)bi * PER_BLK);
    const float4* t4 = reinterpret_cast<const float4*>(targets + (size_t)s * NPS + (size_t)bi * PER_BLK);

    float sum_p = 0.f, sum_t = 0.f, sum_pt = 0.f;
    int   cnt_le = 0;
    float m = -CUDART_INF_F;
    int   n1 = 0, n0 = 0;

    #pragma unroll 8
    for (int k = 0; k < VEC_PER_THREAD; k++) {
        float4 pv = p4[tid + k * THREADS];
        float4 tv = t4[tid + k * THREADS];
        const float pa[4] = {pv.x, pv.y, pv.z, pv.w};
        const float ta[4] = {tv.x, tv.y, tv.z, tv.w};
        #pragma unroll
        for (int j = 0; j < 4; j++) {
            float p = pa[j], t = ta[j];
            sum_p  += p;
            sum_t  += t;
            sum_pt += p * t;
            bool sr = (p > 0.5f);
            cnt_le += sr ? 0 : 1;
            // keep max + reset counts on strictly-greater, then count on equal
            bool gt = (t > m);
            m  = gt ? t : m;
            n1 = gt ? 0 : n1;
            n0 = gt ? 0 : n0;
            bool eq = (t == m);
            n1 += (eq &&  sr) ? 1 : 0;
            n0 += (eq && !sr) ? 1 : 0;
        }
    }

    // warp butterfly reduce
    #pragma unroll
    for (int off = 16; off > 0; off >>= 1) {
        sum_p  += __shfl_xor_sync(0xffffffffu, sum_p,  off);
        sum_t  += __shfl_xor_sync(0xffffffffu, sum_t,  off);
        sum_pt += __shfl_xor_sync(0xffffffffu, sum_pt, off);
        cnt_le += __shfl_xor_sync(0xffffffffu, cnt_le, off);
        float mo  = __shfl_xor_sync(0xffffffffu, m,  off);
        int   n1o = __shfl_xor_sync(0xffffffffu, n1, off);
        int   n0o = __shfl_xor_sync(0xffffffffu, n0, off);
        merge_max(m, n1, n0, mo, n1o, n0o);
    }

    __shared__ Partial sh[THREADS / 32];
    const int wid = tid / 32, lid = tid % 32;
    if (lid == 0) {
        sh[wid] = Partial{sum_p, sum_t, sum_pt, cnt_le, m, n1, n0};
    }
    __syncthreads();

    if (wid == 0) {
        constexpr int NW = THREADS / 32;
        Partial acc;
        if (lid < NW) acc = sh[lid];
        else acc = Partial{0.f, 0.f, 0.f, 0, -CUDART_INF_F, 0, 0};
        sum_p = acc.sum_p; sum_t = acc.sum_t; sum_pt = acc.sum_pt;
        cnt_le = acc.cnt_le; m = acc.m; n1 = acc.n1; n0 = acc.n0;
        #pragma unroll
        for (int off = NW / 2; off > 0; off >>= 1) {
            sum_p  += __shfl_xor_sync(0xffffffffu, sum_p,  off);
            sum_t  += __shfl_xor_sync(0xffffffffu, sum_t,  off);
            sum_pt += __shfl_xor_sync(0xffffffffu, sum_pt, off);
            cnt_le += __shfl_xor_sync(0xffffffffu, cnt_le, off);
            float mo  = __shfl_xor_sync(0xffffffffu, m,  off);
            int   n1o = __shfl_xor_sync(0xffffffffu, n1, off);
            int   n0o = __shfl_xor_sync(0xffffffffu, n0, off);
            merge_max(m, n1, n0, mo, n1o, n0o);
        }
        if (lid == 0) {
            g_partials[s * BPS + bi] = Partial{sum_p, sum_t, sum_pt, cnt_le, m, n1, n0};
        }
    }
}

__global__ __launch_bounds__(B)
void sdl_pass2(float* __restrict__ out) {
    const int b = threadIdx.x;  // one thread per sample

    float sum_p = 0.f, sum_t = 0.f, sum_pt = 0.f;
    int   cnt_le = 0;
    float m = -CUDART_INF_F;
    int   n1 = 0, n0 = 0;

    #pragma unroll
    for (int i = 0; i < BPS; i++) {
        Partial pp = g_partials[b * BPS + i];
        sum_p  += pp.sum_p;
        sum_t  += pp.sum_t;
        sum_pt += pp.sum_pt;
        cnt_le += pp.cnt_le;
        merge_max(m, n1, n0, pp.m, pp.n1, pp.n0);
    }

    // corr = agreements; C = 1 so acc = corr
    const float corr = (float)(n1 + cnt_le - n0);
    const float acc  = corr;  // / C with C=1
    const float dice = 2.0f * (sum_pt + 1.0f) / (sum_p + sum_t + 1.0f);
    const float score = (acc == 1.0f) ? 1.0f : dice;
    float v = 1.0f - score;

    // reduce 64 values: two warps
    #pragma unroll
    for (int off = 16; off > 0; off >>= 1)
        v += __shfl_xor_sync(0xffffffffu, v, off);

    __shared__ float sh2[2];
    if ((b & 31) == 0) sh2[b >> 5] = v;
    __syncthreads();
    if (b == 0) out[0] = (sh2[0] + sh2[1]) / (float)B;
}

extern "C" void kernel_launch(void* const* d_in, const int* in_sizes, int n_in,
                              void* d_out, int out_size) {
    const float* probs   = (const float*)d_in[0];
    const float* targets = (const float*)d_in[1];
    float* out = (float*)d_out;

    sdl_pass1<<<B * BPS, THREADS>>>(probs, targets);
    sdl_pass2<<<1, B>>>(out);
}